// round 1
// baseline (speedup 1.0000x reference)
#include <cuda_runtime.h>
#include <cuda_bf16.h>

#define HW 1024

// ---------------- scratch (__device__ globals: alloc-guard-safe) ----------------
__device__ float g_cat [8u * 1024u * HW];   // 32 MB: [y0|y1|y2|y3] channel-concat layout
__device__ float g_z   [8u * 256u  * HW];   //  8 MB: 3x3 conv output
__device__ float g_qkv [8u * 768u  * HW];   // 24 MB
__device__ float g_atto[8u * 256u  * HW];   //  8 MB: attention output
__device__ float g_scale[2048];
__device__ float g_bias [2048];

__device__ __forceinline__ float silu_f(float v) { return v / (1.f + __expf(-v)); }

// ---------------- BN fold: scale = g*rsqrt(v+eps), bias = b - m*scale ----------------
__global__ void fold_bn_kernel(const float* __restrict__ cv1,
                               const float* __restrict__ cv2,
                               const float* __restrict__ mcv1,
                               const float* __restrict__ mcv2)
{
    int c = blockIdx.x * 256 + threadIdx.x;
    if (c >= 2048) return;
    const float* p; int C, lc;
    if (c < 512)        { p = cv1;  C = 512; lc = c; }
    else if (c < 1024)  { p = cv2;  C = 512; lc = c - 512; }
    else if (c < 1536)  { int i = (c - 1024) >> 8; p = mcv1 + i * 1024; C = 256; lc = (c - 1024) & 255; }
    else                { int i = (c - 1536) >> 8; p = mcv2 + i * 1024; C = 256; lc = (c - 1536) & 255; }
    float g = p[lc], b = p[C + lc], m = p[2 * C + lc], v = p[3 * C + lc];
    float s = g / sqrtf(v + 1e-3f);
    g_scale[c] = s;
    g_bias[c]  = b - m * s;
}

// ---------------- 1x1 conv as GEMM: Out[b,m,n] = sum_k W[m,k]*In[b,k,n] ----------------
// 64x64 tile, K-chunk 16, 256 threads, 4x4 microtile. Optional BN+SiLU+residual epilogue.
__global__ void gemm1x1_kernel(
    const float* __restrict__ In, long inStride,
    const float* __restrict__ W, int K,
    float* __restrict__ Out, long outStride,
    const float* __restrict__ scale, const float* __restrict__ bias,
    const float* __restrict__ Res, long resStride,
    int doSilu)
{
    __shared__ float As[16][68];   // As[k][m]
    __shared__ float Bs[16][64];   // Bs[k][n]
    int b  = blockIdx.z;
    int m0 = blockIdx.y * 64;
    int n0 = blockIdx.x * 64;
    const float* in = In + (long)b * inStride;
    float* out = Out + (long)b * outStride;
    int tid = threadIdx.x;
    int tx = tid & 15, ty = tid >> 4;

    float acc[4][4];
#pragma unroll
    for (int i = 0; i < 4; i++)
#pragma unroll
        for (int j = 0; j < 4; j++) acc[i][j] = 0.f;

    for (int k0 = 0; k0 < K; k0 += 16) {
#pragma unroll
        for (int l = 0; l < 4; l++) {
            int e = tid + l * 256;
            int ka = e & 15, ma = e >> 4;
            As[ka][ma] = W[(long)(m0 + ma) * K + k0 + ka];
            int kb = e >> 6, nb = e & 63;
            Bs[kb][nb] = in[(long)(k0 + kb) * HW + n0 + nb];
        }
        __syncthreads();
#pragma unroll
        for (int kk = 0; kk < 16; kk++) {
            float a0 = As[kk][ty * 4 + 0], a1 = As[kk][ty * 4 + 1];
            float a2 = As[kk][ty * 4 + 2], a3 = As[kk][ty * 4 + 3];
            float c0 = Bs[kk][tx * 4 + 0], c1 = Bs[kk][tx * 4 + 1];
            float c2 = Bs[kk][tx * 4 + 2], c3 = Bs[kk][tx * 4 + 3];
            acc[0][0] += a0 * c0; acc[0][1] += a0 * c1; acc[0][2] += a0 * c2; acc[0][3] += a0 * c3;
            acc[1][0] += a1 * c0; acc[1][1] += a1 * c1; acc[1][2] += a1 * c2; acc[1][3] += a1 * c3;
            acc[2][0] += a2 * c0; acc[2][1] += a2 * c1; acc[2][2] += a2 * c2; acc[2][3] += a2 * c3;
            acc[3][0] += a3 * c0; acc[3][1] += a3 * c1; acc[3][2] += a3 * c2; acc[3][3] += a3 * c3;
        }
        __syncthreads();
    }

#pragma unroll
    for (int i = 0; i < 4; i++) {
        int m = m0 + ty * 4 + i;
        int n = n0 + tx * 4;
        float s = 1.f, bb = 0.f;
        if (scale) { s = scale[m]; bb = bias[m]; }
        float4 r4 = make_float4(0.f, 0.f, 0.f, 0.f);
        if (Res) r4 = *(const float4*)&Res[(long)b * resStride + (long)m * HW + n];
        float v0 = acc[i][0] * s + bb, v1 = acc[i][1] * s + bb;
        float v2 = acc[i][2] * s + bb, v3 = acc[i][3] * s + bb;
        if (doSilu) { v0 = silu_f(v0); v1 = silu_f(v1); v2 = silu_f(v2); v3 = silu_f(v3); }
        v0 += r4.x; v1 += r4.y; v2 += r4.z; v3 += r4.w;
        *(float4*)&out[(long)m * HW + n] = make_float4(v0, v1, v2, v3);
    }
}

// ---------------- direct 3x3 conv, 256->256, pad 1, BN+SiLU ----------------
// Block: 16 co x (32x16 spatial tile). 256 threads: x = tid&31, yq = tid>>5; each
// thread owns 2 rows. ci chunked by 8. Weight LDS (16) amortized over 32 FMAs.
__global__ void conv3x3_kernel(
    const float* __restrict__ In, long inStride,
    const float* __restrict__ W,            // [256][256][3][3]
    float* __restrict__ Out,                // [b][256][1024]
    const float* __restrict__ scale, const float* __restrict__ bias)
{
    __shared__ float ins[8][18][34];
    __shared__ float ws[16][8][9];
    int sp  = blockIdx.x;          // 0..1 (top/bottom 16 rows)
    int cot = blockIdx.y;          // 0..15
    int b   = blockIdx.z;
    int sy = sp * 16;
    const float* in = In + (long)b * inStride;
    int tid = threadIdx.x;
    int x = tid & 31, yq = tid >> 5;

    float acc[2][16];
#pragma unroll
    for (int pl = 0; pl < 2; pl++)
#pragma unroll
        for (int co = 0; co < 16; co++) acc[pl][co] = 0.f;

    for (int c0 = 0; c0 < 256; c0 += 8) {
        for (int e = tid; e < 8 * 18 * 34; e += 256) {
            int ci = e / 612, rem = e % 612;
            int iy = rem / 34, ix = rem % 34;
            int gy = sy + iy - 1, gx = ix - 1;
            float v = 0.f;
            if (gy >= 0 && gy < 32 && gx >= 0 && gx < 32)
                v = in[(long)(c0 + ci) * HW + gy * 32 + gx];
            ins[ci][iy][ix] = v;
        }
        for (int e = tid; e < 16 * 8 * 9; e += 256) {
            int co = e / 72, rem = e % 72;
            int ci = rem / 9, k = rem % 9;
            ws[co][ci][k] = W[(long)(cot * 16 + co) * 2304 + (long)(c0 + ci) * 9 + k];
        }
        __syncthreads();
        for (int ci = 0; ci < 8; ci++) {
#pragma unroll
            for (int ky = 0; ky < 3; ky++)
#pragma unroll
                for (int kx = 0; kx < 3; kx++) {
                    float wv[16];
#pragma unroll
                    for (int co = 0; co < 16; co++) wv[co] = ws[co][ci][ky * 3 + kx];
#pragma unroll
                    for (int pl = 0; pl < 2; pl++) {
                        float v = ins[ci][yq * 2 + pl + ky][x + kx];
#pragma unroll
                        for (int co = 0; co < 16; co++) acc[pl][co] += wv[co] * v;
                    }
                }
        }
        __syncthreads();
    }

#pragma unroll
    for (int pl = 0; pl < 2; pl++) {
        int p = (sy + yq * 2 + pl) * 32 + x;
#pragma unroll
        for (int co = 0; co < 16; co++) {
            int c = cot * 16 + co;
            float v = acc[pl][co] * scale[c] + bias[c];
            Out[((long)b * 256 + c) * HW + p] = silu_f(v);
        }
    }
}

// ---------------- fused flash attention: 4 heads, HD=64, 1024 tokens ----------------
// Block = (b,h, 64-query tile). 256 threads: row r = tid>>2, quad q4 = tid&3.
// Key tiles of 32; r = rw+rh folded into K-tile load. Online softmax.
__global__ void attn_kernel(
    const float* __restrict__ QKV,
    const float* __restrict__ RW,   // [4][64][32]  (per x)
    const float* __restrict__ RH,   // [4][64][32]  (per y)
    float* __restrict__ Outp)       // [b][256][1024]
{
    __shared__ float Qs[64][65];
    __shared__ float Ks[64][33];
    __shared__ float Vs[64][33];
    __shared__ float Ps[64][33];
    int qt = blockIdx.x, h = blockIdx.y, b = blockIdx.z;
    const float* Q  = QKV + (long)b * 768 * HW + (long)(h * 64) * HW;
    const float* Kp = QKV + (long)b * 768 * HW + (long)(256 + h * 64) * HW;
    const float* Vp = QKV + (long)b * 768 * HW + (long)(512 + h * 64) * HW;
    const float* rw = RW + h * 64 * 32;
    const float* rh = RH + h * 64 * 32;
    int tid = threadIdx.x;
    int r = tid >> 2, q4 = tid & 3;

#pragma unroll
    for (int pass = 0; pass < 16; pass++) {
        int idx = tid + pass * 256;
        int d = idx >> 6, rr = idx & 63;
        Qs[rr][d] = Q[(long)d * HW + qt * 64 + rr];
    }
    __syncthreads();

    float m_run = -1e30f, l_run = 0.f;
    float acc[16];
#pragma unroll
    for (int i = 0; i < 16; i++) acc[i] = 0.f;

    for (int jt = 0; jt < 32; jt++) {
        int j0 = jt * 32;
#pragma unroll
        for (int pass = 0; pass < 8; pass++) {
            int idx = tid + pass * 256;
            int d = idx >> 5, jj = idx & 31;
            int j = j0 + jj;
            Ks[d][jj] = Kp[(long)d * HW + j] + rw[d * 32 + (j & 31)] + rh[d * 32 + (j >> 5)];
            Vs[d][jj] = Vp[(long)d * HW + j];
        }
        __syncthreads();

        float s[8];
#pragma unroll
        for (int c = 0; c < 8; c++) s[c] = 0.f;
        for (int d = 0; d < 64; d++) {
            float qv = Qs[r][d];
#pragma unroll
            for (int c = 0; c < 8; c++) s[c] += qv * Ks[d][q4 * 8 + c];
        }
        float mloc = -1e30f;
#pragma unroll
        for (int c = 0; c < 8; c++) { s[c] *= 0.125f; mloc = fmaxf(mloc, s[c]); }
        mloc = fmaxf(mloc, __shfl_xor_sync(0xffffffffu, mloc, 1));
        mloc = fmaxf(mloc, __shfl_xor_sync(0xffffffffu, mloc, 2));
        float m_new = fmaxf(m_run, mloc);
        float p[8], lsum = 0.f;
#pragma unroll
        for (int c = 0; c < 8; c++) { p[c] = __expf(s[c] - m_new); lsum += p[c]; }
        lsum += __shfl_xor_sync(0xffffffffu, lsum, 1);
        lsum += __shfl_xor_sync(0xffffffffu, lsum, 2);
        float alpha = __expf(m_run - m_new);
#pragma unroll
        for (int i = 0; i < 16; i++) acc[i] *= alpha;
        l_run = l_run * alpha + lsum;
        m_run = m_new;
#pragma unroll
        for (int c = 0; c < 8; c++) Ps[r][q4 * 8 + c] = p[c];
        __syncwarp();
        for (int j = 0; j < 32; j++) {
            float pv = Ps[r][j];
#pragma unroll
            for (int dd = 0; dd < 16; dd++) acc[dd] += pv * Vs[q4 * 16 + dd][j];
        }
        __syncthreads();
    }

    float inv = 1.f / l_run;
#pragma unroll
    for (int dd = 0; dd < 16; dd++) {
        int d = q4 * 16 + dd;
        Outp[((long)b * 256 + h * 64 + d) * HW + qt * 64 + r] = acc[dd] * inv;
    }
}

// ---------------- launch ----------------
extern "C" void kernel_launch(void* const* d_in, const int* in_sizes, int n_in,
                              void* d_out, int out_size)
{
    const float* x      = (const float*)d_in[0];
    const float* cv1_w  = (const float*)d_in[1];
    const float* cv1_bn = (const float*)d_in[2];
    const float* cv2_w  = (const float*)d_in[3];
    const float* cv2_bn = (const float*)d_in[4];
    const float* mcv1w  = (const float*)d_in[5];
    const float* mcv1bn = (const float*)d_in[6];
    const float* mqkvw  = (const float*)d_in[7];
    const float* mrw    = (const float*)d_in[8];
    const float* mrh    = (const float*)d_in[9];
    const float* mcv2w  = (const float*)d_in[10];
    const float* mcv2bn = (const float*)d_in[11];
    float* out = (float*)d_out;

    float *cat, *z, *qkv, *atto, *scl, *bia;
    cudaGetSymbolAddress((void**)&cat,  g_cat);
    cudaGetSymbolAddress((void**)&z,    g_z);
    cudaGetSymbolAddress((void**)&qkv,  g_qkv);
    cudaGetSymbolAddress((void**)&atto, g_atto);
    cudaGetSymbolAddress((void**)&scl,  g_scale);
    cudaGetSymbolAddress((void**)&bia,  g_bias);

    fold_bn_kernel<<<8, 256>>>(cv1_bn, cv2_bn, mcv1bn, mcv2bn);

    // t = cbs(x, cv1_w): 512->512, written into CAT channels [0..512)
    gemm1x1_kernel<<<dim3(16, 8, 8), 256>>>(
        x, (long)512 * HW, cv1_w, 512, cat, (long)1024 * HW,
        scl + 0, bia + 0, nullptr, 0, 1);

    for (int i = 0; i < 2; i++) {
        long yin  = (long)(i == 0 ? 256 : 512) * HW;   // input channels of this iter
        long yout = (long)(512 + i * 256) * HW;        // output channels of this iter
        // z = cbs(yi, 3x3)
        conv3x3_kernel<<<dim3(2, 16, 8), 256>>>(
            cat + yin, (long)1024 * HW, mcv1w + (long)i * 256 * 256 * 9, z,
            scl + 1024 + i * 256, bia + 1024 + i * 256);
        // qkv = conv1x1(z), 256->768, no BN/act
        gemm1x1_kernel<<<dim3(16, 12, 8), 256>>>(
            z, (long)256 * HW, mqkvw + (long)i * 768 * 256, 256, qkv, (long)768 * HW,
            nullptr, nullptr, nullptr, 0, 0);
        // fused attention with relpos
        attn_kernel<<<dim3(16, 4, 8), 256>>>(
            qkv, mrw + (long)i * 4 * 64 * 32, mrh + (long)i * 4 * 64 * 32, atto);
        // y_{i+2} = yi + silu(bn(conv1x1(atto)))
        gemm1x1_kernel<<<dim3(16, 4, 8), 256>>>(
            atto, (long)256 * HW, mcv2w + (long)i * 256 * 256, 256, cat + yout, (long)1024 * HW,
            scl + 1536 + i * 256, bia + 1536 + i * 256, cat + yin, (long)1024 * HW, 1);
    }

    // final: cbs(concat(ys), cv2_w): 1024->512
    gemm1x1_kernel<<<dim3(16, 8, 8), 256>>>(
        cat, (long)1024 * HW, cv2_w, 1024, out, (long)512 * HW,
        scl + 512, bia + 512, nullptr, 0, 1);
}

// round 3
// speedup vs baseline: 1.4197x; 1.4197x over previous
#include <cuda_runtime.h>
#include <cuda_bf16.h>
#include <cstdint>

#define HW 1024

// ---------------- scratch (__device__ globals: alloc-guard-safe) ----------------
__device__ float g_cat [8u * 1024u * HW];   // 32 MB: [y0|y1|y2|y3] channel-concat
__device__ float g_z   [8u * 256u  * HW];   //  8 MB: 3x3 conv output
__device__ float g_qkv [8u * 768u  * HW];   // 24 MB
__device__ float g_atto[8u * 256u  * HW];   //  8 MB
__device__ float g_scale[2048];
__device__ float g_bias [2048];
// bf16 split buffers
__device__ __nv_bfloat16 g_Whi[589824];          // max 256*2304
__device__ __nv_bfloat16 g_Wlo[589824];
__device__ __nv_bfloat16 g_Bhi[18874368];        // max 8*1024*2304
__device__ __nv_bfloat16 g_Blo[18874368];

__device__ __forceinline__ float silu_f(float v) { return v / (1.f + __expf(-v)); }

__device__ __forceinline__ uint32_t smem_u32(const void* p) {
    uint32_t a;
    asm("{ .reg .u64 t; cvta.to.shared.u64 t, %1; cvt.u32.u64 %0, t; }" : "=r"(a) : "l"(p));
    return a;
}
#define SWZ128(o) ((o) ^ (((o) >> 3) & 0x70))

__device__ __forceinline__ void ldsm_x4(uint32_t* r, uint32_t a) {
    asm volatile("ldmatrix.sync.aligned.m8n8.x4.shared.b16 {%0,%1,%2,%3}, [%4];"
        : "=r"(r[0]), "=r"(r[1]), "=r"(r[2]), "=r"(r[3]) : "r"(a));
}
__device__ __forceinline__ void ldsm_x2(uint32_t* r, uint32_t a) {
    asm volatile("ldmatrix.sync.aligned.m8n8.x2.shared.b16 {%0,%1}, [%2];"
        : "=r"(r[0]), "=r"(r[1]) : "r"(a));
}
__device__ __forceinline__ void mma16816(float* d, const uint32_t* a, const uint32_t* b) {
    asm volatile("mma.sync.aligned.m16n8k16.row.col.f32.bf16.bf16.f32 "
        "{%0,%1,%2,%3}, {%4,%5,%6,%7}, {%8,%9}, {%0,%1,%2,%3};"
        : "+f"(d[0]), "+f"(d[1]), "+f"(d[2]), "+f"(d[3])
        : "r"(a[0]), "r"(a[1]), "r"(a[2]), "r"(a[3]), "r"(b[0]), "r"(b[1]));
}

// ---------------- BN fold ----------------
__global__ void fold_bn_kernel(const float* __restrict__ cv1, const float* __restrict__ cv2,
                               const float* __restrict__ mcv1, const float* __restrict__ mcv2)
{
    int c = blockIdx.x * 256 + threadIdx.x;
    if (c >= 2048) return;
    const float* p; int C, lc;
    if (c < 512)        { p = cv1;  C = 512; lc = c; }
    else if (c < 1024)  { p = cv2;  C = 512; lc = c - 512; }
    else if (c < 1536)  { int i = (c - 1024) >> 8; p = mcv1 + i * 1024; C = 256; lc = (c - 1024) & 255; }
    else                { int i = (c - 1536) >> 8; p = mcv2 + i * 1024; C = 256; lc = (c - 1536) & 255; }
    float g = p[lc], b = p[C + lc], m = p[2 * C + lc], v = p[3 * C + lc];
    float s = g / sqrtf(v + 1e-3f);
    g_scale[c] = s;
    g_bias[c]  = b - m * s;
}

// ---------------- weight converter: fp32 -> bf16 hi/lo (optional 3x3 k-reorder) ----------------
__global__ void convW_kernel(const float* __restrict__ W, int M, int K, int isConv,
                             __nv_bfloat16* __restrict__ Whi, __nv_bfloat16* __restrict__ Wlo)
{
    long e = (long)blockIdx.x * 256 + threadIdx.x;
    if (e >= (long)M * K) return;
    long m = e / K, k = e % K;
    float v;
    if (isConv) { int off = (int)(k >> 8), ci = (int)(k & 255); v = W[m * 2304 + ci * 9 + off]; }
    else v = W[e];
    __nv_bfloat16 h = __float2bfloat16(v);
    Whi[e] = h;
    Wlo[e] = __float2bfloat16(v - __bfloat162float(h));
}

// ---------------- activation converter: [b][K][HW] -> transposed bf16 [b][n][K] hi/lo ----------------
__global__ void convB_kernel(const float* __restrict__ In, long inStride, int K,
                             __nv_bfloat16* __restrict__ Bhi, __nv_bfloat16* __restrict__ Blo)
{
    __shared__ float t[32][33];
    int n0 = blockIdx.x * 32, k0 = blockIdx.y * 32, b = blockIdx.z;
    int tx = threadIdx.x, ty = threadIdx.y;
    const float* in = In + (long)b * inStride;
#pragma unroll
    for (int yy = 0; yy < 32; yy += 8)
        t[yy + ty][tx] = in[(long)(k0 + yy + ty) * HW + n0 + tx];
    __syncthreads();
#pragma unroll
    for (int yy = 0; yy < 32; yy += 8) {
        int n = n0 + yy + ty, k = k0 + tx;
        float v = t[tx][yy + ty];
        long o = ((long)b * 1024 + n) * K + k;
        __nv_bfloat16 h = __float2bfloat16(v);
        Bhi[o] = h;
        Blo[o] = __float2bfloat16(v - __bfloat162float(h));
    }
}

// ---------------- im2col converter for 3x3 conv: k = (ky*3+kx)*256 + ci ----------------
__global__ void im2colB_kernel(const float* __restrict__ In, long inStride,
                               __nv_bfloat16* __restrict__ Bhi, __nv_bfloat16* __restrict__ Blo)
{
    __shared__ float t[32][33];
    int y = blockIdx.x, ci0 = blockIdx.y * 32;
    int off = blockIdx.z % 9, b = blockIdx.z / 9;
    int ky = off / 3, kx = off % 3;
    int tx = threadIdx.x, ty = threadIdx.y;
    const float* in = In + (long)b * inStride;
    int yy = y + ky - 1;
    int xx = tx + kx - 1;
    bool vy = (yy >= 0 && yy < 32), vx = (xx >= 0 && xx < 32);
#pragma unroll
    for (int d = 0; d < 32; d += 8) {
        float v = 0.f;
        if (vy && vx) v = in[(long)(ci0 + d + ty) * HW + yy * 32 + xx];
        t[d + ty][tx] = v;
    }
    __syncthreads();
#pragma unroll
    for (int d = 0; d < 32; d += 8) {
        int n = y * 32 + d + ty;
        int k = off * 256 + ci0 + tx;
        float v = t[tx][d + ty];
        long o = ((long)b * 1024 + n) * 2304 + k;
        __nv_bfloat16 h = __float2bfloat16(v);
        Bhi[o] = h;
        Blo[o] = __float2bfloat16(v - __bfloat162float(h));
    }
}

// ---------------- warp-MMA GEMM: Out[b,m,n] = sum_k W[m,k] * In[k,n] ----------------
// A = W bf16 hi/lo [M][K] K-major; B = transposed act [n][K] K-major.
// CTA tile M=128, N=128, K-chunk 64; double-buffered SW128 SMEM; 8 warps, warp tile 64x32.
// Split-3: Ah*Bh + Al*Bh + Ah*Bl.
#define STAGE_BYTES 65536
#define TG_SMEM (2 * STAGE_BYTES)

__device__ __forceinline__ void tg_load_chunk(
    char* smc, int s, int tid,
    const uint4* __restrict__ wHi, const uint4* __restrict__ wLo,
    const uint4* __restrict__ bHi, const uint4* __restrict__ bLo,
    int m0, int n0, int K8, int c)
{
    char* base = smc + s * STAGE_BYTES;
#pragma unroll
    for (int l = 0; l < 4; l++) {
        int e = tid + l * 256;
        int r = e >> 3, j = e & 7;
        long gi = (long)(m0 + r) * K8 + c * 8 + j;
        uint4 vh = wHi[gi];
        uint4 vl = wLo[gi];
        uint32_t off = SWZ128((uint32_t)(r * 128 + j * 16));
        *(uint4*)(base + off) = vh;
        *(uint4*)(base + 16384 + off) = vl;
    }
#pragma unroll
    for (int l = 0; l < 4; l++) {
        int e = tid + l * 256;
        int r = e >> 3, j = e & 7;
        long gi = (long)(n0 + r) * K8 + c * 8 + j;
        uint4 vh = bHi[gi];
        uint4 vl = bLo[gi];
        uint32_t off = SWZ128((uint32_t)(r * 128 + j * 16));
        *(uint4*)(base + 32768 + off) = vh;
        *(uint4*)(base + 49152 + off) = vl;
    }
}

extern __shared__ char tg_smem[];

__global__ void __launch_bounds__(256) mgemm_kernel(
    const __nv_bfloat16* __restrict__ Bhi, const __nv_bfloat16* __restrict__ Blo,
    const __nv_bfloat16* __restrict__ Whi, const __nv_bfloat16* __restrict__ Wlo,
    int K,
    float* __restrict__ Out, long outStride,
    const float* __restrict__ scale, const float* __restrict__ bias,
    const float* __restrict__ Res, long resStride,
    int doSilu)
{
    int b = blockIdx.z, m0 = blockIdx.y * 128, n0 = blockIdx.x * 128;
    int tid = threadIdx.x, wid = tid >> 5, lane = tid & 31;
    int warp_m = wid & 1, warp_n = wid >> 1;   // 2 x 4 warps, warp tile 64x32
    uint32_t smb = smem_u32(tg_smem);

    int K8 = K >> 3;
    const uint4* wHi = (const uint4*)Whi;
    const uint4* wLo = (const uint4*)Wlo;
    const uint4* bHi = (const uint4*)(Bhi + (long)b * 1024 * K);
    const uint4* bLo = (const uint4*)(Blo + (long)b * 1024 * K);

    float acc[4][4][4];
#pragma unroll
    for (int i = 0; i < 4; i++)
#pragma unroll
        for (int j = 0; j < 4; j++)
#pragma unroll
            for (int r = 0; r < 4; r++) acc[i][j][r] = 0.f;

    int nChunks = K >> 6;
    tg_load_chunk(tg_smem, 0, tid, wHi, wLo, bHi, bLo, m0, n0, K8, 0);
    __syncthreads();

    // precomputed intra-tile fragment offsets (lane-dependent)
    int aRowL = warp_m * 64 + (lane & 7) + (lane & 8);       // + mt*16
    int aColL = ((lane >> 4) & 1) * 16;                      // + ks*32
    int li = lane & 15;
    int bRowL = warp_n * 32 + (li & 7);                      // + nt*8
    int bColL = ((li >> 3) & 1) * 16;                        // + ks*32

    for (int c = 0; c < nChunks; c++) {
        int s = c & 1;
        if (c + 1 < nChunks)
            tg_load_chunk(tg_smem, s ^ 1, tid, wHi, wLo, bHi, bLo, m0, n0, K8, c + 1);

        uint32_t base = smb + s * STAGE_BYTES;
        uint32_t aH = base, aL = base + 16384, bH = base + 32768, bL = base + 49152;
#pragma unroll
        for (int ks = 0; ks < 4; ks++) {
            uint32_t ah[4][4], bh[4][2];
#pragma unroll
            for (int mt = 0; mt < 4; mt++) {
                uint32_t off = SWZ128((uint32_t)((aRowL + mt * 16) * 128 + aColL + ks * 32));
                ldsm_x4(ah[mt], aH + off);
            }
#pragma unroll
            for (int nt = 0; nt < 4; nt++) {
                uint32_t off = SWZ128((uint32_t)((bRowL + nt * 8) * 128 + bColL + ks * 32));
                ldsm_x2(bh[nt], bH + off);
            }
#pragma unroll
            for (int mt = 0; mt < 4; mt++)
#pragma unroll
                for (int nt = 0; nt < 4; nt++) mma16816(acc[mt][nt], ah[mt], bh[nt]);

            uint32_t al[4][4];
#pragma unroll
            for (int mt = 0; mt < 4; mt++) {
                uint32_t off = SWZ128((uint32_t)((aRowL + mt * 16) * 128 + aColL + ks * 32));
                ldsm_x4(al[mt], aL + off);
            }
#pragma unroll
            for (int mt = 0; mt < 4; mt++)
#pragma unroll
                for (int nt = 0; nt < 4; nt++) mma16816(acc[mt][nt], al[mt], bh[nt]);

            uint32_t bl[4][2];
#pragma unroll
            for (int nt = 0; nt < 4; nt++) {
                uint32_t off = SWZ128((uint32_t)((bRowL + nt * 8) * 128 + bColL + ks * 32));
                ldsm_x2(bl[nt], bL + off);
            }
#pragma unroll
            for (int mt = 0; mt < 4; mt++)
#pragma unroll
                for (int nt = 0; nt < 4; nt++) mma16816(acc[mt][nt], ah[mt], bl[nt]);
        }
        __syncthreads();
    }

    // ---- epilogue: direct register stores (float2), fused BN/SiLU/residual ----
#pragma unroll
    for (int mt = 0; mt < 4; mt++) {
        int mb = m0 + warp_m * 64 + mt * 16 + (lane >> 2);
#pragma unroll
        for (int h2 = 0; h2 < 2; h2++) {
            int m = mb + h2 * 8;
            float s = 1.f, bb = 0.f;
            if (scale) { s = scale[m]; bb = bias[m]; }
            long rowOff = (long)b * outStride + (long)m * HW;
            long resOff = Res ? ((long)b * resStride + (long)m * HW) : 0;
#pragma unroll
            for (int nt = 0; nt < 4; nt++) {
                int n = n0 + warp_n * 32 + nt * 8 + (lane & 3) * 2;
                float v0 = acc[mt][nt][h2 * 2 + 0] * s + bb;
                float v1 = acc[mt][nt][h2 * 2 + 1] * s + bb;
                if (doSilu) { v0 = silu_f(v0); v1 = silu_f(v1); }
                if (Res) {
                    float2 r2 = *(const float2*)&Res[resOff + n];
                    v0 += r2.x; v1 += r2.y;
                }
                *(float2*)&Out[rowOff + n] = make_float2(v0, v1);
            }
        }
    }
}

// ---------------- fused flash attention (fp32) ----------------
__global__ void attn_kernel(
    const float* __restrict__ QKV,
    const float* __restrict__ RW, const float* __restrict__ RH,
    float* __restrict__ Outp)
{
    __shared__ float Qs[64][65];
    __shared__ float Ks[64][33];
    __shared__ float Vs[64][33];
    __shared__ float Ps[64][33];
    int qt = blockIdx.x, h = blockIdx.y, b = blockIdx.z;
    const float* Q  = QKV + (long)b * 768 * HW + (long)(h * 64) * HW;
    const float* Kp = QKV + (long)b * 768 * HW + (long)(256 + h * 64) * HW;
    const float* Vp = QKV + (long)b * 768 * HW + (long)(512 + h * 64) * HW;
    const float* rw = RW + h * 64 * 32;
    const float* rh = RH + h * 64 * 32;
    int tid = threadIdx.x;
    int r = tid >> 2, q4 = tid & 3;

#pragma unroll
    for (int pass = 0; pass < 16; pass++) {
        int idx = tid + pass * 256;
        int d = idx >> 6, rr = idx & 63;
        Qs[rr][d] = Q[(long)d * HW + qt * 64 + rr];
    }
    __syncthreads();

    float m_run = -1e30f, l_run = 0.f;
    float acc[16];
#pragma unroll
    for (int i = 0; i < 16; i++) acc[i] = 0.f;

    for (int jt = 0; jt < 32; jt++) {
        int j0 = jt * 32;
#pragma unroll
        for (int pass = 0; pass < 8; pass++) {
            int idx = tid + pass * 256;
            int d = idx >> 5, jj = idx & 31;
            int j = j0 + jj;
            Ks[d][jj] = Kp[(long)d * HW + j] + rw[d * 32 + (j & 31)] + rh[d * 32 + (j >> 5)];
            Vs[d][jj] = Vp[(long)d * HW + j];
        }
        __syncthreads();

        float s[8];
#pragma unroll
        for (int c = 0; c < 8; c++) s[c] = 0.f;
        for (int d = 0; d < 64; d++) {
            float qv = Qs[r][d];
#pragma unroll
            for (int c = 0; c < 8; c++) s[c] += qv * Ks[d][q4 * 8 + c];
        }
        float mloc = -1e30f;
#pragma unroll
        for (int c = 0; c < 8; c++) { s[c] *= 0.125f; mloc = fmaxf(mloc, s[c]); }
        mloc = fmaxf(mloc, __shfl_xor_sync(0xffffffffu, mloc, 1));
        mloc = fmaxf(mloc, __shfl_xor_sync(0xffffffffu, mloc, 2));
        float m_new = fmaxf(m_run, mloc);
        float p[8], lsum = 0.f;
#pragma unroll
        for (int c = 0; c < 8; c++) { p[c] = __expf(s[c] - m_new); lsum += p[c]; }
        lsum += __shfl_xor_sync(0xffffffffu, lsum, 1);
        lsum += __shfl_xor_sync(0xffffffffu, lsum, 2);
        float alpha = __expf(m_run - m_new);
#pragma unroll
        for (int i = 0; i < 16; i++) acc[i] *= alpha;
        l_run = l_run * alpha + lsum;
        m_run = m_new;
#pragma unroll
        for (int c = 0; c < 8; c++) Ps[r][q4 * 8 + c] = p[c];
        __syncwarp();
        for (int j = 0; j < 32; j++) {
            float pv = Ps[r][j];
#pragma unroll
            for (int dd = 0; dd < 16; dd++) acc[dd] += pv * Vs[q4 * 16 + dd][j];
        }
        __syncthreads();
    }

    float inv = 1.f / l_run;
#pragma unroll
    for (int dd = 0; dd < 16; dd++) {
        int d = q4 * 16 + dd;
        Outp[((long)b * 256 + h * 64 + d) * HW + qt * 64 + r] = acc[dd] * inv;
    }
}

// ---------------- launch ----------------
extern "C" void kernel_launch(void* const* d_in, const int* in_sizes, int n_in,
                              void* d_out, int out_size)
{
    const float* x      = (const float*)d_in[0];
    const float* cv1_w  = (const float*)d_in[1];
    const float* cv1_bn = (const float*)d_in[2];
    const float* cv2_w  = (const float*)d_in[3];
    const float* cv2_bn = (const float*)d_in[4];
    const float* mcv1w  = (const float*)d_in[5];
    const float* mcv1bn = (const float*)d_in[6];
    const float* mqkvw  = (const float*)d_in[7];
    const float* mrw    = (const float*)d_in[8];
    const float* mrh    = (const float*)d_in[9];
    const float* mcv2w  = (const float*)d_in[10];
    const float* mcv2bn = (const float*)d_in[11];
    float* out = (float*)d_out;

    float *cat, *z, *qkv, *atto, *scl, *bia;
    __nv_bfloat16 *whi, *wlo, *bhi, *blo;
    cudaGetSymbolAddress((void**)&cat,  g_cat);
    cudaGetSymbolAddress((void**)&z,    g_z);
    cudaGetSymbolAddress((void**)&qkv,  g_qkv);
    cudaGetSymbolAddress((void**)&atto, g_atto);
    cudaGetSymbolAddress((void**)&scl,  g_scale);
    cudaGetSymbolAddress((void**)&bia,  g_bias);
    cudaGetSymbolAddress((void**)&whi,  g_Whi);
    cudaGetSymbolAddress((void**)&wlo,  g_Wlo);
    cudaGetSymbolAddress((void**)&bhi,  g_Bhi);
    cudaGetSymbolAddress((void**)&blo,  g_Blo);

    static int smemSet = 0;
    if (!smemSet) {
        cudaFuncSetAttribute(mgemm_kernel, cudaFuncAttributeMaxDynamicSharedMemorySize, TG_SMEM);
        smemSet = 1;
    }

    fold_bn_kernel<<<8, 256>>>(cv1_bn, cv2_bn, mcv1bn, mcv2bn);

    // ---- cv1: 512 -> 512, BN+SiLU, into cat[0:512) ----
    convW_kernel<<<(512 * 512 + 255) / 256, 256>>>(cv1_w, 512, 512, 0, whi, wlo);
    convB_kernel<<<dim3(32, 16, 8), dim3(32, 8)>>>(x, (long)512 * HW, 512, bhi, blo);
    mgemm_kernel<<<dim3(8, 4, 8), 256, TG_SMEM>>>(
        bhi, blo, whi, wlo, 512, cat, (long)1024 * HW,
        scl + 0, bia + 0, nullptr, 0, 1);

    for (int i = 0; i < 2; i++) {
        long yin  = (long)(i == 0 ? 256 : 512) * HW;
        long yout = (long)(512 + i * 256) * HW;

        // z = cbs(yi, 3x3) as implicit GEMM, K=2304
        convW_kernel<<<(256 * 2304 + 255) / 256, 256>>>(
            mcv1w + (long)i * 256 * 2304, 256, 2304, 1, whi, wlo);
        im2colB_kernel<<<dim3(32, 8, 72), dim3(32, 8)>>>(cat + yin, (long)1024 * HW, bhi, blo);
        mgemm_kernel<<<dim3(8, 2, 8), 256, TG_SMEM>>>(
            bhi, blo, whi, wlo, 2304, z, (long)256 * HW,
            scl + 1024 + i * 256, bia + 1024 + i * 256, nullptr, 0, 1);

        // qkv = conv1x1(z), 256 -> 768
        convW_kernel<<<(768 * 256 + 255) / 256, 256>>>(
            mqkvw + (long)i * 768 * 256, 768, 256, 0, whi, wlo);
        convB_kernel<<<dim3(32, 8, 8), dim3(32, 8)>>>(z, (long)256 * HW, 256, bhi, blo);
        mgemm_kernel<<<dim3(8, 6, 8), 256, TG_SMEM>>>(
            bhi, blo, whi, wlo, 256, qkv, (long)768 * HW,
            nullptr, nullptr, nullptr, 0, 0);

        // fused attention with relpos
        attn_kernel<<<dim3(16, 4, 8), 256>>>(
            qkv, mrw + (long)i * 4 * 64 * 32, mrh + (long)i * 4 * 64 * 32, atto);

        // y_{i+2} = yi + silu(bn(conv1x1(atto)))
        convW_kernel<<<(256 * 256 + 255) / 256, 256>>>(
            mcv2w + (long)i * 256 * 256, 256, 256, 0, whi, wlo);
        convB_kernel<<<dim3(32, 8, 8), dim3(32, 8)>>>(atto, (long)256 * HW, 256, bhi, blo);
        mgemm_kernel<<<dim3(8, 2, 8), 256, TG_SMEM>>>(
            bhi, blo, whi, wlo, 256, cat + yout, (long)1024 * HW,
            scl + 1536 + i * 256, bia + 1536 + i * 256, cat + yin, (long)1024 * HW, 1);
    }

    // ---- final: 1024 -> 512, BN+SiLU ----
    convW_kernel<<<(512 * 1024 + 255) / 256, 256>>>(cv2_w, 512, 1024, 0, whi, wlo);
    convB_kernel<<<dim3(32, 32, 8), dim3(32, 8)>>>(cat, (long)1024 * HW, 1024, bhi, blo);
    mgemm_kernel<<<dim3(8, 4, 8), 256, TG_SMEM>>>(
        bhi, blo, whi, wlo, 1024, out, (long)512 * HW,
        scl + 512, bia + 512, nullptr, 0, 1);
}

// round 4
// speedup vs baseline: 4.2437x; 2.9891x over previous
#include <cuda_runtime.h>
#include <cuda_bf16.h>
#include <cstdint>

#define HW 1024

// ---------------- scratch (__device__ globals: alloc-guard-safe) ----------------
__device__ float g_cat [8u * 1024u * HW];   // 32 MB
__device__ float g_z   [8u * 256u  * HW];   //  8 MB
__device__ float g_qkv [8u * 768u  * HW];   // 24 MB
__device__ float g_atto[8u * 256u  * HW];   //  8 MB
__device__ float g_scale[2048];
__device__ float g_bias [2048];
__device__ __nv_bfloat16 g_Whi[589824];
__device__ __nv_bfloat16 g_Wlo[589824];
__device__ __nv_bfloat16 g_Bhi[18874368];
__device__ __nv_bfloat16 g_Blo[18874368];

// offsets (elements) inside g_Bhi/g_Blo for attention operands
#define QT_OFF 0
#define KT_OFF 2097152
#define V_OFF  4194304

__device__ __forceinline__ float silu_f(float v) { return v / (1.f + __expf(-v)); }

__device__ __forceinline__ uint32_t smem_u32(const void* p) {
    uint32_t a;
    asm("{ .reg .u64 t; cvta.to.shared.u64 t, %1; cvt.u32.u64 %0, t; }" : "=r"(a) : "l"(p));
    return a;
}
#define SWZ128(o) ((o) ^ (((o) >> 3) & 0x70))
#define SWZ64(o)  ((o) ^ (((o) >> 3) & 0x30))

__device__ __forceinline__ void ldsm_x4(uint32_t* r, uint32_t a) {
    asm volatile("ldmatrix.sync.aligned.m8n8.x4.shared.b16 {%0,%1,%2,%3}, [%4];"
        : "=r"(r[0]), "=r"(r[1]), "=r"(r[2]), "=r"(r[3]) : "r"(a));
}
__device__ __forceinline__ void ldsm_x2(uint32_t* r, uint32_t a) {
    asm volatile("ldmatrix.sync.aligned.m8n8.x2.shared.b16 {%0,%1}, [%2];"
        : "=r"(r[0]), "=r"(r[1]) : "r"(a));
}
__device__ __forceinline__ void mma16816(float* d, const uint32_t* a, const uint32_t* b) {
    asm volatile("mma.sync.aligned.m16n8k16.row.col.f32.bf16.bf16.f32 "
        "{%0,%1,%2,%3}, {%4,%5,%6,%7}, {%8,%9}, {%0,%1,%2,%3};"
        : "+f"(d[0]), "+f"(d[1]), "+f"(d[2]), "+f"(d[3])
        : "r"(a[0]), "r"(a[1]), "r"(a[2]), "r"(a[3]), "r"(b[0]), "r"(b[1]));
}
__device__ __forceinline__ void cpa16(uint32_t d, const void* s) {
    asm volatile("cp.async.cg.shared.global [%0], [%1], 16;" :: "r"(d), "l"(s));
}
#define CPA_COMMIT() asm volatile("cp.async.commit_group;" ::: "memory")
#define CPA_WAIT1()  asm volatile("cp.async.wait_group 1;" ::: "memory")
#define CPA_WAIT0()  asm volatile("cp.async.wait_group 0;" ::: "memory")

__device__ __forceinline__ uint32_t packbf(float lo, float hi) {
    uint32_t r;
    asm("cvt.rn.bf16x2.f32 %0, %1, %2;" : "=r"(r) : "f"(hi), "f"(lo));
    return r;
}

// ---------------- BN fold ----------------
__global__ void fold_bn_kernel(const float* __restrict__ cv1, const float* __restrict__ cv2,
                               const float* __restrict__ mcv1, const float* __restrict__ mcv2)
{
    int c = blockIdx.x * 256 + threadIdx.x;
    if (c >= 2048) return;
    const float* p; int C, lc;
    if (c < 512)        { p = cv1;  C = 512; lc = c; }
    else if (c < 1024)  { p = cv2;  C = 512; lc = c - 512; }
    else if (c < 1536)  { int i = (c - 1024) >> 8; p = mcv1 + i * 1024; C = 256; lc = (c - 1024) & 255; }
    else                { int i = (c - 1536) >> 8; p = mcv2 + i * 1024; C = 256; lc = (c - 1536) & 255; }
    float g = p[lc], b = p[C + lc], m = p[2 * C + lc], v = p[3 * C + lc];
    float s = g / sqrtf(v + 1e-3f);
    g_scale[c] = s;
    g_bias[c]  = b - m * s;
}

// ---------------- weight converter ----------------
__global__ void convW_kernel(const float* __restrict__ W, int M, int K, int isConv,
                             __nv_bfloat16* __restrict__ Whi, __nv_bfloat16* __restrict__ Wlo)
{
    long e = (long)blockIdx.x * 256 + threadIdx.x;
    if (e >= (long)M * K) return;
    long m = e / K, k = e % K;
    float v;
    if (isConv) { int off = (int)(k >> 8), ci = (int)(k & 255); v = W[m * 2304 + ci * 9 + off]; }
    else v = W[e];
    __nv_bfloat16 h = __float2bfloat16(v);
    Whi[e] = h;
    Wlo[e] = __float2bfloat16(v - __bfloat162float(h));
}

// ---------------- activation converter: [b][K][HW] -> [b][n][K] hi/lo ----------------
__global__ void convB_kernel(const float* __restrict__ In, long inStride, int K,
                             __nv_bfloat16* __restrict__ Bhi, __nv_bfloat16* __restrict__ Blo)
{
    __shared__ float t[32][33];
    int n0 = blockIdx.x * 32, k0 = blockIdx.y * 32, b = blockIdx.z;
    int tx = threadIdx.x, ty = threadIdx.y;
    const float* in = In + (long)b * inStride;
#pragma unroll
    for (int yy = 0; yy < 32; yy += 8)
        t[yy + ty][tx] = in[(long)(k0 + yy + ty) * HW + n0 + tx];
    __syncthreads();
#pragma unroll
    for (int yy = 0; yy < 32; yy += 8) {
        int n = n0 + yy + ty, k = k0 + tx;
        float v = t[tx][yy + ty];
        long o = ((long)b * 1024 + n) * K + k;
        __nv_bfloat16 h = __float2bfloat16(v);
        Bhi[o] = h;
        Blo[o] = __float2bfloat16(v - __bfloat162float(h));
    }
}

// ---------------- im2col converter: k = (ky*3+kx)*256 + ci ----------------
__global__ void im2colB_kernel(const float* __restrict__ In, long inStride,
                               __nv_bfloat16* __restrict__ Bhi, __nv_bfloat16* __restrict__ Blo)
{
    __shared__ float t[32][33];
    int y = blockIdx.x, ci0 = blockIdx.y * 32;
    int off = blockIdx.z % 9, b = blockIdx.z / 9;
    int ky = off / 3, kx = off % 3;
    int tx = threadIdx.x, ty = threadIdx.y;
    const float* in = In + (long)b * inStride;
    int yy = y + ky - 1;
    int xx = tx + kx - 1;
    bool vy = (yy >= 0 && yy < 32), vx = (xx >= 0 && xx < 32);
#pragma unroll
    for (int d = 0; d < 32; d += 8) {
        float v = 0.f;
        if (vy && vx) v = in[(long)(ci0 + d + ty) * HW + yy * 32 + xx];
        t[d + ty][tx] = v;
    }
    __syncthreads();
#pragma unroll
    for (int d = 0; d < 32; d += 8) {
        int n = y * 32 + d + ty;
        int k = off * 256 + ci0 + tx;
        float v = t[tx][d + ty];
        long o = ((long)b * 1024 + n) * 2304 + k;
        __nv_bfloat16 h = __float2bfloat16(v);
        Bhi[o] = h;
        Blo[o] = __float2bfloat16(v - __bfloat162float(h));
    }
}

// ---------------- warp-MMA GEMM v2: cp.async, K-chunk 32, SW64, 2 CTAs/SM ----------------
#define MG_STAGE 32768
#define MG_SMEM  65536

__device__ __forceinline__ void mg_load(uint32_t smb, int tid,
    const uint4* __restrict__ wHi, const uint4* __restrict__ wLo,
    const uint4* __restrict__ bHi, const uint4* __restrict__ bLo,
    int m0, int n0, int K16, int c, uint32_t stOff)
{
    uint32_t sb = smb + stOff;
    int r = tid >> 1;
    int j = (tid & 1) * 2;
    uint32_t o0 = SWZ64((uint32_t)(r * 64 + j * 16));
    uint32_t o1 = SWZ64((uint32_t)(r * 64 + (j + 1) * 16));
    const uint4* a;
    a = wHi + (long)(m0 + r) * K16 + c * 4 + j;
    cpa16(sb + o0, a); cpa16(sb + o1, a + 1);
    a = wLo + (long)(m0 + r) * K16 + c * 4 + j;
    cpa16(sb + 8192 + o0, a); cpa16(sb + 8192 + o1, a + 1);
    a = bHi + (long)(n0 + r) * K16 + c * 4 + j;
    cpa16(sb + 16384 + o0, a); cpa16(sb + 16384 + o1, a + 1);
    a = bLo + (long)(n0 + r) * K16 + c * 4 + j;
    cpa16(sb + 24576 + o0, a); cpa16(sb + 24576 + o1, a + 1);
}

extern __shared__ char mg_smem[];

__global__ void __launch_bounds__(256, 2) mgemm_kernel(
    const __nv_bfloat16* __restrict__ Bhi, const __nv_bfloat16* __restrict__ Blo,
    const __nv_bfloat16* __restrict__ Whi, const __nv_bfloat16* __restrict__ Wlo,
    int K,
    float* __restrict__ Out, long outStride,
    const float* __restrict__ scale, const float* __restrict__ bias,
    const float* __restrict__ Res, long resStride,
    int doSilu)
{
    int b = blockIdx.z, m0 = blockIdx.y * 128, n0 = blockIdx.x * 128;
    int tid = threadIdx.x, wid = tid >> 5, lane = tid & 31;
    int warp_m = wid & 1, warp_n = wid >> 1;
    uint32_t smb = smem_u32(mg_smem);

    int K16 = K >> 3;
    const uint4* wHi = (const uint4*)Whi;
    const uint4* wLo = (const uint4*)Wlo;
    const uint4* bHi = (const uint4*)(Bhi + (long)b * 1024 * K);
    const uint4* bLo = (const uint4*)(Blo + (long)b * 1024 * K);

    float acc[4][4][4];
#pragma unroll
    for (int i = 0; i < 4; i++)
#pragma unroll
        for (int j = 0; j < 4; j++)
#pragma unroll
            for (int r = 0; r < 4; r++) acc[i][j][r] = 0.f;

    int nChunks = K >> 5;
    mg_load(smb, tid, wHi, wLo, bHi, bLo, m0, n0, K16, 0, 0);
    CPA_COMMIT();

    int aRowL = warp_m * 64 + (lane & 7) + (lane & 8);
    int aColL = ((lane >> 4) & 1) * 16;
    int li = lane & 15;
    int bRowL = warp_n * 32 + (li & 7);
    int bColL = (li >> 3) * 16;

    for (int c = 0; c < nChunks; c++) {
        int s = c & 1;
        if (c + 1 < nChunks) {
            mg_load(smb, tid, wHi, wLo, bHi, bLo, m0, n0, K16, c + 1, (uint32_t)((s ^ 1) * MG_STAGE));
            CPA_COMMIT();
            CPA_WAIT1();
        } else {
            CPA_WAIT0();
        }
        __syncthreads();

        uint32_t base = smb + s * MG_STAGE;
#pragma unroll
        for (int ks = 0; ks < 2; ks++) {
            uint32_t ah[4][4], bh2[4][2];
#pragma unroll
            for (int mt = 0; mt < 4; mt++)
                ldsm_x4(ah[mt], base + SWZ64((uint32_t)((aRowL + mt * 16) * 64 + aColL + ks * 32)));
#pragma unroll
            for (int nt = 0; nt < 4; nt++)
                ldsm_x2(bh2[nt], base + 16384 + SWZ64((uint32_t)((bRowL + nt * 8) * 64 + bColL + ks * 32)));
#pragma unroll
            for (int mt = 0; mt < 4; mt++)
#pragma unroll
                for (int nt = 0; nt < 4; nt++) mma16816(acc[mt][nt], ah[mt], bh2[nt]);

            uint32_t al[4][4];
#pragma unroll
            for (int mt = 0; mt < 4; mt++)
                ldsm_x4(al[mt], base + 8192 + SWZ64((uint32_t)((aRowL + mt * 16) * 64 + aColL + ks * 32)));
#pragma unroll
            for (int mt = 0; mt < 4; mt++)
#pragma unroll
                for (int nt = 0; nt < 4; nt++) mma16816(acc[mt][nt], al[mt], bh2[nt]);

            uint32_t bl2[4][2];
#pragma unroll
            for (int nt = 0; nt < 4; nt++)
                ldsm_x2(bl2[nt], base + 24576 + SWZ64((uint32_t)((bRowL + nt * 8) * 64 + bColL + ks * 32)));
#pragma unroll
            for (int mt = 0; mt < 4; mt++)
#pragma unroll
                for (int nt = 0; nt < 4; nt++) mma16816(acc[mt][nt], ah[mt], bl2[nt]);
        }
        __syncthreads();
    }

#pragma unroll
    for (int mt = 0; mt < 4; mt++) {
        int mb = m0 + warp_m * 64 + mt * 16 + (lane >> 2);
#pragma unroll
        for (int h2 = 0; h2 < 2; h2++) {
            int m = mb + h2 * 8;
            float s = 1.f, bb = 0.f;
            if (scale) { s = scale[m]; bb = bias[m]; }
            long rowOff = (long)b * outStride + (long)m * HW;
            long resOff = Res ? ((long)b * resStride + (long)m * HW) : 0;
#pragma unroll
            for (int nt = 0; nt < 4; nt++) {
                int n = n0 + warp_n * 32 + nt * 8 + (lane & 3) * 2;
                float v0 = acc[mt][nt][h2 * 2 + 0] * s + bb;
                float v1 = acc[mt][nt][h2 * 2 + 1] * s + bb;
                if (doSilu) { v0 = silu_f(v0); v1 = silu_f(v1); }
                if (Res) {
                    float2 r2 = *(const float2*)&Res[resOff + n];
                    v0 += r2.x; v1 += r2.y;
                }
                *(float2*)&Out[rowOff + n] = make_float2(v0, v1);
            }
        }
    }
}

// ---------------- attention converter: qkv fp32 -> qT/kT(+relpos)/v bf16 hi/lo ----------------
// qT/kT: [bh][i=1024][d=64]; v: [bh][d=64][j=1024]. Q scaled by 0.125.
__global__ void convAttn_kernel(const float* __restrict__ QKV,
                                const float* __restrict__ RW, const float* __restrict__ RH,
                                __nv_bfloat16* __restrict__ Hi, __nv_bfloat16* __restrict__ Lo)
{
    __shared__ float tq[32][33], tk[32][33];
    int it = blockIdx.x, dt = blockIdx.y, bh = blockIdx.z;
    int b = bh >> 2, hh = bh & 3;
    int tx = threadIdx.x, ty = threadIdx.y;
    const float* base = QKV + (long)b * 768 * HW;
#pragma unroll
    for (int l = 0; l < 4; l++) {
        int d = dt * 32 + ty + l * 8;
        int ch = hh * 64 + d;
        float qv = base[(long)ch * HW + it * 32 + tx] * 0.125f;
        float kv = base[(long)(256 + ch) * HW + it * 32 + tx] + RW[ch * 32 + tx] + RH[ch * 32 + it];
        float vv = base[(long)(512 + ch) * HW + it * 32 + tx];
        tq[ty + l * 8][tx] = qv;
        tk[ty + l * 8][tx] = kv;
        long vo = V_OFF + ((long)bh * 64 + d) * 1024 + it * 32 + tx;
        __nv_bfloat16 vh = __float2bfloat16(vv);
        Hi[vo] = vh;
        Lo[vo] = __float2bfloat16(vv - __bfloat162float(vh));
    }
    __syncthreads();
#pragma unroll
    for (int l = 0; l < 4; l++) {
        int i = it * 32 + ty + l * 8;
        int d = dt * 32 + tx;
        float qv = tq[tx][ty + l * 8];
        float kv = tk[tx][ty + l * 8];
        long qo = ((long)bh * 1024 + i) * 64 + d;
        __nv_bfloat16 qh = __float2bfloat16(qv);
        Hi[QT_OFF + qo] = qh;
        Lo[QT_OFF + qo] = __float2bfloat16(qv - __bfloat162float(qh));
        __nv_bfloat16 kh = __float2bfloat16(kv);
        Hi[KT_OFF + qo] = kh;
        Lo[KT_OFF + qo] = __float2bfloat16(kv - __bfloat162float(kh));
    }
}

// ---------------- MMA flash attention ----------------
// grid (8 qtiles, 4 h, 8 b), 256 threads. Warp w owns query rows w*16..w*16+15.
// smem: stage s at s*65536: Kh 0, Kl 16384, Vh 32768 (2 subtiles of 8192), Vl 49152.
// Q at 131072: Qh, Ql(+16384). Total 163840.
#define AT_SMEM 163840

__device__ __forceinline__ void kv_load(uint32_t smb, int tid,
    const __nv_bfloat16* __restrict__ kTh, const __nv_bfloat16* __restrict__ kTl,
    const __nv_bfloat16* __restrict__ vH, const __nv_bfloat16* __restrict__ vL,
    int bh, int t, uint32_t stOff)
{
    uint32_t kb = smb + stOff;
    const uint4* kh4 = (const uint4*)(kTh + ((long)bh * 1024 + t * 128) * 64);
    const uint4* kl4 = (const uint4*)(kTl + ((long)bh * 1024 + t * 128) * 64);
    int r = tid >> 1, j0 = (tid & 1) * 4;
#pragma unroll
    for (int j = 0; j < 4; j++) {
        uint32_t off = SWZ128((uint32_t)(r * 128 + (j0 + j) * 16));
        cpa16(kb + off, kh4 + (long)r * 8 + j0 + j);
        cpa16(kb + 16384 + off, kl4 + (long)r * 8 + j0 + j);
    }
    const uint4* vh4 = (const uint4*)(vH + (long)bh * 65536 + t * 128);
    const uint4* vl4 = (const uint4*)(vL + (long)bh * 65536 + t * 128);
    int d = tid >> 2, jc0 = (tid & 3) * 4;
#pragma unroll
    for (int j = 0; j < 4; j++) {
        int jc = jc0 + j;
        uint32_t off = (uint32_t)((jc >> 3) * 8192) + SWZ128((uint32_t)(d * 128 + (jc & 7) * 16));
        cpa16(kb + 32768 + off, vh4 + (long)d * 128 + jc);
        cpa16(kb + 49152 + off, vl4 + (long)d * 128 + jc);
    }
}

extern __shared__ char at_smem[];

__global__ void __launch_bounds__(256) attn_mma_kernel(
    const __nv_bfloat16* __restrict__ Hi, const __nv_bfloat16* __restrict__ Lo,
    float* __restrict__ Outp)
{
    int qt = blockIdx.x, h = blockIdx.y, b = blockIdx.z;
    int bh = b * 4 + h;
    int tid = threadIdx.x, wid = tid >> 5, lane = tid & 31, li = lane & 15;
    uint32_t smb = smem_u32(at_smem);

    const __nv_bfloat16* qTh = Hi + QT_OFF;
    const __nv_bfloat16* qTl = Lo + QT_OFF;
    const __nv_bfloat16* kTh = Hi + KT_OFF;
    const __nv_bfloat16* kTl = Lo + KT_OFF;
    const __nv_bfloat16* vH  = Hi + V_OFF;
    const __nv_bfloat16* vL  = Lo + V_OFF;

    // Q tile load (i rows 128, d cols 64)
    {
        const uint4* qh4 = (const uint4*)(qTh + ((long)bh * 1024 + qt * 128) * 64);
        const uint4* ql4 = (const uint4*)(qTl + ((long)bh * 1024 + qt * 128) * 64);
        int r = tid >> 1, j0 = (tid & 1) * 4;
        uint32_t qb = smb + 131072;
#pragma unroll
        for (int j = 0; j < 4; j++) {
            uint32_t off = SWZ128((uint32_t)(r * 128 + (j0 + j) * 16));
            cpa16(qb + off, qh4 + (long)r * 8 + j0 + j);
            cpa16(qb + 16384 + off, ql4 + (long)r * 8 + j0 + j);
        }
    }
    CPA_COMMIT();
    kv_load(smb, tid, kTh, kTl, vH, vL, bh, 0, 0);
    CPA_COMMIT();
    CPA_WAIT1();
    __syncthreads();

    uint32_t qfh[4][4], qfl[4][4];
    {
        int aRow = wid * 16 + (lane & 7) + (lane & 8);
        int aCol = ((lane >> 4) & 1) * 16;
#pragma unroll
        for (int ks = 0; ks < 4; ks++) {
            uint32_t off = SWZ128((uint32_t)(aRow * 128 + aCol + ks * 32));
            ldsm_x4(qfh[ks], smb + 131072 + off);
            ldsm_x4(qfl[ks], smb + 131072 + 16384 + off);
        }
    }

    float oacc[8][4];
#pragma unroll
    for (int i = 0; i < 8; i++)
#pragma unroll
        for (int j = 0; j < 4; j++) oacc[i][j] = 0.f;
    float m0 = -1e30f, m1 = -1e30f, l0 = 0.f, l1 = 0.f;

    for (int t = 0; t < 8; t++) {
        int s = t & 1;
        if (t < 7) {
            kv_load(smb, tid, kTh, kTl, vH, vL, bh, t + 1, (uint32_t)((s ^ 1) * 65536));
            CPA_COMMIT();
            CPA_WAIT1();
        } else {
            CPA_WAIT0();
        }
        __syncthreads();

        uint32_t kb = smb + s * 65536;
        float sacc[16][4];
#pragma unroll
        for (int i = 0; i < 16; i++)
#pragma unroll
            for (int j = 0; j < 4; j++) sacc[i][j] = 0.f;

#pragma unroll
        for (int nt = 0; nt < 16; nt++) {
            int rowB = nt * 8 + (li & 7);
            uint32_t colB = (uint32_t)((li >> 3) * 16);
#pragma unroll
            for (int ks = 0; ks < 4; ks++) {
                uint32_t off = SWZ128((uint32_t)(rowB * 128 + colB + ks * 32));
                uint32_t kh2[2], kl2[2];
                ldsm_x2(kh2, kb + off);
                ldsm_x2(kl2, kb + 16384 + off);
                mma16816(sacc[nt], qfh[ks], kh2);
                mma16816(sacc[nt], qfl[ks], kh2);
                mma16816(sacc[nt], qfh[ks], kl2);
            }
        }

        // online softmax (rows r0 = lane>>2, r1 = r0+8 within warp tile)
        float mx0 = m0, mx1 = m1;
#pragma unroll
        for (int nt = 0; nt < 16; nt++) {
            mx0 = fmaxf(mx0, fmaxf(sacc[nt][0], sacc[nt][1]));
            mx1 = fmaxf(mx1, fmaxf(sacc[nt][2], sacc[nt][3]));
        }
        mx0 = fmaxf(mx0, __shfl_xor_sync(0xffffffffu, mx0, 1));
        mx0 = fmaxf(mx0, __shfl_xor_sync(0xffffffffu, mx0, 2));
        mx1 = fmaxf(mx1, __shfl_xor_sync(0xffffffffu, mx1, 1));
        mx1 = fmaxf(mx1, __shfl_xor_sync(0xffffffffu, mx1, 2));
        float a0 = __expf(m0 - mx0), a1 = __expf(m1 - mx1);
        m0 = mx0; m1 = mx1;

        float ls0 = 0.f, ls1 = 0.f;
        uint32_t pah[8][4], pal[8][4];
#pragma unroll
        for (int kj = 0; kj < 8; kj++) {
            float p00 = __expf(sacc[2 * kj][0] - m0);
            float p01 = __expf(sacc[2 * kj][1] - m0);
            float p02 = __expf(sacc[2 * kj][2] - m1);
            float p03 = __expf(sacc[2 * kj][3] - m1);
            float p10 = __expf(sacc[2 * kj + 1][0] - m0);
            float p11 = __expf(sacc[2 * kj + 1][1] - m0);
            float p12 = __expf(sacc[2 * kj + 1][2] - m1);
            float p13 = __expf(sacc[2 * kj + 1][3] - m1);
            ls0 += p00 + p01 + p10 + p11;
            ls1 += p02 + p03 + p12 + p13;
            pah[kj][0] = packbf(p00, p01);
            pah[kj][1] = packbf(p02, p03);
            pah[kj][2] = packbf(p10, p11);
            pah[kj][3] = packbf(p12, p13);
            float q00 = p00 - __bfloat162float(__float2bfloat16(p00));
            float q01 = p01 - __bfloat162float(__float2bfloat16(p01));
            float q02 = p02 - __bfloat162float(__float2bfloat16(p02));
            float q03 = p03 - __bfloat162float(__float2bfloat16(p03));
            float q10 = p10 - __bfloat162float(__float2bfloat16(p10));
            float q11 = p11 - __bfloat162float(__float2bfloat16(p11));
            float q12 = p12 - __bfloat162float(__float2bfloat16(p12));
            float q13 = p13 - __bfloat162float(__float2bfloat16(p13));
            pal[kj][0] = packbf(q00, q01);
            pal[kj][1] = packbf(q02, q03);
            pal[kj][2] = packbf(q10, q11);
            pal[kj][3] = packbf(q12, q13);
        }
        ls0 += __shfl_xor_sync(0xffffffffu, ls0, 1);
        ls0 += __shfl_xor_sync(0xffffffffu, ls0, 2);
        ls1 += __shfl_xor_sync(0xffffffffu, ls1, 1);
        ls1 += __shfl_xor_sync(0xffffffffu, ls1, 2);
        l0 = l0 * a0 + ls0;
        l1 = l1 * a1 + ls1;
#pragma unroll
        for (int dt = 0; dt < 8; dt++) {
            oacc[dt][0] *= a0; oacc[dt][1] *= a0;
            oacc[dt][2] *= a1; oacc[dt][3] *= a1;
        }

        // O += P * V
#pragma unroll
        for (int dt = 0; dt < 8; dt++) {
            int rowV = dt * 8 + (li & 7);
#pragma unroll
            for (int kj = 0; kj < 8; kj++) {
                uint32_t off = (uint32_t)((kj >> 2) * 8192) +
                               SWZ128((uint32_t)(rowV * 128 + (li >> 3) * 16 + (kj & 3) * 32));
                uint32_t vh2[2], vl2[2];
                ldsm_x2(vh2, kb + 32768 + off);
                ldsm_x2(vl2, kb + 49152 + off);
                mma16816(oacc[dt], pah[kj], vh2);
                mma16816(oacc[dt], pal[kj], vh2);
                mma16816(oacc[dt], pah[kj], vl2);
            }
        }
        __syncthreads();
    }

    // epilogue: smem transpose -> coalesced writes
    float i0 = 1.f / l0, i1 = 1.f / l1;
    float* stg = (float*)at_smem;   // [128][66]
    int r0 = wid * 16 + (lane >> 2);
#pragma unroll
    for (int dt = 0; dt < 8; dt++) {
        int d = dt * 8 + (lane & 3) * 2;
        stg[r0 * 66 + d]       = oacc[dt][0] * i0;
        stg[r0 * 66 + d + 1]   = oacc[dt][1] * i0;
        stg[(r0 + 8) * 66 + d]     = oacc[dt][2] * i1;
        stg[(r0 + 8) * 66 + d + 1] = oacc[dt][3] * i1;
    }
    __syncthreads();
    for (int e = tid; e < 8192; e += 256) {
        int d = e >> 7, i = e & 127;
        Outp[((long)b * 256 + h * 64 + d) * HW + qt * 128 + i] = stg[i * 66 + d];
    }
}

// ---------------- launch ----------------
extern "C" void kernel_launch(void* const* d_in, const int* in_sizes, int n_in,
                              void* d_out, int out_size)
{
    const float* x      = (const float*)d_in[0];
    const float* cv1_w  = (const float*)d_in[1];
    const float* cv1_bn = (const float*)d_in[2];
    const float* cv2_w  = (const float*)d_in[3];
    const float* cv2_bn = (const float*)d_in[4];
    const float* mcv1w  = (const float*)d_in[5];
    const float* mcv1bn = (const float*)d_in[6];
    const float* mqkvw  = (const float*)d_in[7];
    const float* mrw    = (const float*)d_in[8];
    const float* mrh    = (const float*)d_in[9];
    const float* mcv2w  = (const float*)d_in[10];
    const float* mcv2bn = (const float*)d_in[11];
    float* out = (float*)d_out;

    float *cat, *z, *qkv, *atto, *scl, *bia;
    __nv_bfloat16 *whi, *wlo, *bhi, *blo;
    cudaGetSymbolAddress((void**)&cat,  g_cat);
    cudaGetSymbolAddress((void**)&z,    g_z);
    cudaGetSymbolAddress((void**)&qkv,  g_qkv);
    cudaGetSymbolAddress((void**)&atto, g_atto);
    cudaGetSymbolAddress((void**)&scl,  g_scale);
    cudaGetSymbolAddress((void**)&bia,  g_bias);
    cudaGetSymbolAddress((void**)&whi,  g_Whi);
    cudaGetSymbolAddress((void**)&wlo,  g_Wlo);
    cudaGetSymbolAddress((void**)&bhi,  g_Bhi);
    cudaGetSymbolAddress((void**)&blo,  g_Blo);

    cudaFuncSetAttribute(mgemm_kernel, cudaFuncAttributeMaxDynamicSharedMemorySize, MG_SMEM);
    cudaFuncSetAttribute(attn_mma_kernel, cudaFuncAttributeMaxDynamicSharedMemorySize, AT_SMEM);

    fold_bn_kernel<<<8, 256>>>(cv1_bn, cv2_bn, mcv1bn, mcv2bn);

    // ---- cv1: 512 -> 512, BN+SiLU, into cat[0:512) ----
    convW_kernel<<<(512 * 512 + 255) / 256, 256>>>(cv1_w, 512, 512, 0, whi, wlo);
    convB_kernel<<<dim3(32, 16, 8), dim3(32, 8)>>>(x, (long)512 * HW, 512, bhi, blo);
    mgemm_kernel<<<dim3(8, 4, 8), 256, MG_SMEM>>>(
        bhi, blo, whi, wlo, 512, cat, (long)1024 * HW,
        scl + 0, bia + 0, nullptr, 0, 1);

    for (int i = 0; i < 2; i++) {
        long yin  = (long)(i == 0 ? 256 : 512) * HW;
        long yout = (long)(512 + i * 256) * HW;

        // z = cbs(yi, 3x3) as implicit GEMM, K=2304
        convW_kernel<<<(256 * 2304 + 255) / 256, 256>>>(
            mcv1w + (long)i * 256 * 2304, 256, 2304, 1, whi, wlo);
        im2colB_kernel<<<dim3(32, 8, 72), dim3(32, 8)>>>(cat + yin, (long)1024 * HW, bhi, blo);
        mgemm_kernel<<<dim3(8, 2, 8), 256, MG_SMEM>>>(
            bhi, blo, whi, wlo, 2304, z, (long)256 * HW,
            scl + 1024 + i * 256, bia + 1024 + i * 256, nullptr, 0, 1);

        // qkv = conv1x1(z), 256 -> 768
        convW_kernel<<<(768 * 256 + 255) / 256, 256>>>(
            mqkvw + (long)i * 768 * 256, 768, 256, 0, whi, wlo);
        convB_kernel<<<dim3(32, 8, 8), dim3(32, 8)>>>(z, (long)256 * HW, 256, bhi, blo);
        mgemm_kernel<<<dim3(8, 6, 8), 256, MG_SMEM>>>(
            bhi, blo, whi, wlo, 256, qkv, (long)768 * HW,
            nullptr, nullptr, nullptr, 0, 0);

        // attention operand conversion + MMA flash attention
        convAttn_kernel<<<dim3(32, 2, 32), dim3(32, 8)>>>(
            qkv, mrw + (long)i * 8192, mrh + (long)i * 8192, bhi, blo);
        attn_mma_kernel<<<dim3(8, 4, 8), 256, AT_SMEM>>>(bhi, blo, atto);

        // y_{i+2} = yi + silu(bn(conv1x1(atto)))
        convW_kernel<<<(256 * 256 + 255) / 256, 256>>>(
            mcv2w + (long)i * 256 * 256, 256, 256, 0, whi, wlo);
        convB_kernel<<<dim3(32, 8, 8), dim3(32, 8)>>>(atto, (long)256 * HW, 256, bhi, blo);
        mgemm_kernel<<<dim3(8, 2, 8), 256, MG_SMEM>>>(
            bhi, blo, whi, wlo, 256, cat + yout, (long)1024 * HW,
            scl + 1536 + i * 256, bia + 1536 + i * 256, cat + yin, (long)1024 * HW, 1);
    }

    // ---- final: 1024 -> 512, BN+SiLU ----
    convW_kernel<<<(512 * 1024 + 255) / 256, 256>>>(cv2_w, 512, 1024, 0, whi, wlo);
    convB_kernel<<<dim3(32, 32, 8), dim3(32, 8)>>>(cat, (long)1024 * HW, 1024, bhi, blo);
    mgemm_kernel<<<dim3(8, 4, 8), 256, MG_SMEM>>>(
        bhi, blo, whi, wlo, 1024, out, (long)512 * HW,
        scl + 512, bia + 512, nullptr, 0, 1);
}